// round 3
// baseline (speedup 1.0000x reference)
#include <cuda_runtime.h>
#include <math.h>

// Problem constants
#define BB 2
#define LL 1024
#define CAx 512
#define CSx 384
#define CZx 64
#define HHx 16
#define DDx 32
#define MMx (BB*LL)   // 2048

// ---------------- scratch (static device memory; no allocations) ----------------
__device__ float g_aln[MMx*CAx];          // 4 MB
__device__ float g_sln[MMx*CSx];          // 3 MB
__device__ float g_anorm[MMx*CAx];        // 4 MB
__device__ float g_t1[MMx*CAx];           // 4 MB
__device__ float g_t2[MMx*CAx];           // 4 MB
__device__ float g_q[BB*HHx*LL*DDx];      // 4 MB
__device__ float g_k[BB*HHx*LL*DDx];      // 4 MB
__device__ float g_v[BB*HHx*LL*DDx];      // 4 MB
__device__ float g_gate[MMx*CAx];         // 4 MB
__device__ float g_o1[MMx*CAx];           // 4 MB
__device__ float g_o2[MMx*CAx];           // 4 MB
__device__ float g_maskf[MMx];
__device__ float g_bias[(size_t)BB*HHx*LL*LL];  // 128 MB; reused: bias -> logits -> probs

// ---------------- reductions ----------------
__device__ __forceinline__ float warpRedSum(float v){
    #pragma unroll
    for(int o=16;o>0;o>>=1) v += __shfl_xor_sync(0xffffffffu, v, o);
    return v;
}
__device__ __forceinline__ float warpRedMax(float v){
    #pragma unroll
    for(int o=16;o>0;o>>=1) v = fmaxf(v, __shfl_xor_sync(0xffffffffu, v, o));
    return v;
}
// 256-thread block reduce, result broadcast to all threads. sm must hold >= 9 floats.
__device__ float blockRedSum(float v, float* sm){
    int lane = threadIdx.x & 31, w = threadIdx.x >> 5;
    v = warpRedSum(v);
    if(lane==0) sm[w] = v;
    __syncthreads();
    if(w==0){
        float x = (lane<8)? sm[lane] : 0.f;
        x = warpRedSum(x);
        if(lane==0) sm[8] = x;
    }
    __syncthreads();
    float r = sm[8];
    __syncthreads();
    return r;
}
__device__ float blockRedMax(float v, float* sm){
    int lane = threadIdx.x & 31, w = threadIdx.x >> 5;
    v = warpRedMax(v);
    if(lane==0) sm[w] = v;
    __syncthreads();
    if(w==0){
        float x = (lane<8)? sm[lane] : -3.4e38f;
        x = warpRedMax(x);
        if(lane==0) sm[8] = x;
    }
    __syncthreads();
    float r = sm[8];
    __syncthreads();
    return r;
}

__device__ __forceinline__ float sigm(float v){ return 1.f/(1.f+expf(-v)); }

// ---------------- mask -> float ----------------
// Mask arrives as a 4-byte dtype (int32 0/1 or float32 0.0/1.0). Nonzero-word
// test is correct for both encodings.
__global__ void k_maskf(const unsigned int* __restrict__ mk){
    int i = blockIdx.x*256 + threadIdx.x;
    if(i < MMx) g_maskf[i] = (mk[i] != 0u) ? 1.f : 0.f;
}

// ---------------- LayerNorm of a (512) and s (384, scaled) ----------------
__global__ void __launch_bounds__(256) k_ln(const float* __restrict__ a,
                                            const float* __restrict__ s,
                                            const float* __restrict__ lns){
    __shared__ float sm[16];
    int m = blockIdx.x, t = threadIdx.x;
    // a: 512
    const float* ar = a + (size_t)m*CAx;
    float x0 = ar[t], x1 = ar[t+256];
    float sum  = blockRedSum(x0 + x1, sm);
    float sum2 = blockRedSum(x0*x0 + x1*x1, sm);
    float mean = sum * (1.f/CAx);
    float var  = sum2 * (1.f/CAx) - mean*mean;
    float r = rsqrtf(var + 1e-5f);
    g_aln[(size_t)m*CAx + t]       = (x0-mean)*r;
    g_aln[(size_t)m*CAx + t + 256] = (x1-mean)*r;
    // s: 384
    const float* sr = s + (size_t)m*CSx;
    float y0 = sr[t];
    float y1 = (t < 128) ? sr[t+256] : 0.f;
    float ss  = blockRedSum(y0 + y1, sm);
    float ss2 = blockRedSum(y0*y0 + y1*y1, sm);
    float mn = ss * (1.f/CSx);
    float vr = ss2 * (1.f/CSx) - mn*mn;
    float rr = rsqrtf(vr + 1e-5f);
    g_sln[(size_t)m*CSx + t] = (y0-mn)*rr*lns[t];
    if(t < 128) g_sln[(size_t)m*CSx + t + 256] = (y1-mn)*rr*lns[t+256];
}

// ---------------- generic SGEMM: out = A[M,K] @ W[N,K]^T (+bias), epilogues ----------------
// EPI: 0 = plain; 1 = head layout [B,H,L,D]; 2 = sigmoid; 3 = sigmoid(v)*aux1*aux2[m]
template<int EPI>
__global__ void __launch_bounds__(256) gemm64(const float* __restrict__ A,
                                              const float* __restrict__ W,
                                              const float* __restrict__ bias,
                                              float* __restrict__ out,
                                              int N, int K,
                                              const float* __restrict__ aux1,
                                              const float* __restrict__ aux2){
    __shared__ float As[16][68];
    __shared__ float Ws[16][68];
    int t = threadIdx.x;
    int m0 = blockIdx.y*64, n0 = blockIdx.x*64;
    int ty = t>>4, tx = t&15;
    int lr = t>>2, lc = (t&3)*4;
    const float* Ap = A + (size_t)(m0+lr)*K + lc;
    const float* Wp = W + (size_t)(n0+lr)*K + lc;
    float acc[4][4] = {};
    for(int kt=0; kt<K; kt+=16){
        float4 av = *(const float4*)(Ap + kt);
        float4 wv = *(const float4*)(Wp + kt);
        As[lc+0][lr]=av.x; As[lc+1][lr]=av.y; As[lc+2][lr]=av.z; As[lc+3][lr]=av.w;
        Ws[lc+0][lr]=wv.x; Ws[lc+1][lr]=wv.y; Ws[lc+2][lr]=wv.z; Ws[lc+3][lr]=wv.w;
        __syncthreads();
        #pragma unroll
        for(int kk=0; kk<16; kk++){
            float4 a4 = *(const float4*)&As[kk][ty*4];
            float4 b4 = *(const float4*)&Ws[kk][tx*4];
            float aa[4] = {a4.x,a4.y,a4.z,a4.w};
            float bb[4] = {b4.x,b4.y,b4.z,b4.w};
            #pragma unroll
            for(int i=0;i<4;i++)
                #pragma unroll
                for(int j=0;j<4;j++)
                    acc[i][j] += aa[i]*bb[j];
        }
        __syncthreads();
    }
    #pragma unroll
    for(int i=0;i<4;i++){
        #pragma unroll
        for(int j=0;j<4;j++){
            int m = m0 + ty*4 + i;
            int n = n0 + tx*4 + j;
            float v = acc[i][j] + (bias ? bias[n] : 0.f);
            if(EPI==0){
                out[(size_t)m*N + n] = v;
            } else if(EPI==1){
                int b = m>>10, l = m&1023, h = n>>5, d = n&31;
                out[(((size_t)(b*HHx+h))*LL + l)*DDx + d] = v;
            } else if(EPI==2){
                out[(size_t)m*N + n] = sigm(v);
            } else {
                out[(size_t)m*N + n] = sigm(v) * aux1[(size_t)m*N + n] * aux2[m];
            }
        }
    }
}

// ---------------- a_norm = sigmoid(t1)*a_ln + t2 ----------------
__global__ void k_anorm(){
    int i = blockIdx.x*256 + threadIdx.x;   // grid covers M*CA
    g_anorm[i] = sigm(g_t1[i]) * g_aln[i] + g_t2[i];
}

// ---------------- pair bias: g_bias[b,h,q,k] = ln(z[b,q,k,:], scale) . wz[h,:] ----------------
__global__ void __launch_bounds__(256) k_bias(const float* __restrict__ z,
                                              const float* __restrict__ lnz,
                                              const float* __restrict__ wz){
    __shared__ float swz[HHx*CZx];
    __shared__ float sscale[CZx];
    int t = threadIdx.x;
    for(int i=t; i<HHx*CZx; i+=256) swz[i] = wz[i];
    if(t < CZx) sscale[t] = lnz[t];
    __syncthreads();
    size_t r = (size_t)blockIdx.x*256 + t;            // 0 .. B*L*L-1
    const float4* zp = (const float4*)(z + r*CZx);
    float4 zv[16];
    float sum = 0.f, sum2 = 0.f;
    #pragma unroll
    for(int i=0;i<16;i++){
        zv[i] = zp[i];
        sum  += zv[i].x + zv[i].y + zv[i].z + zv[i].w;
        sum2 += zv[i].x*zv[i].x + zv[i].y*zv[i].y + zv[i].z*zv[i].z + zv[i].w*zv[i].w;
    }
    float mean = sum * (1.f/CZx);
    float var  = sum2 * (1.f/CZx) - mean*mean;
    float rs = rsqrtf(var + 1e-5f);
    #pragma unroll
    for(int i=0;i<16;i++){
        zv[i].x = (zv[i].x-mean)*rs*sscale[4*i+0];
        zv[i].y = (zv[i].y-mean)*rs*sscale[4*i+1];
        zv[i].z = (zv[i].z-mean)*rs*sscale[4*i+2];
        zv[i].w = (zv[i].w-mean)*rs*sscale[4*i+3];
    }
    int b  = (int)(r >> 20);
    int qq = (int)((r >> 10) & 1023);
    int kk = (int)(r & 1023);
    size_t obase = (((size_t)(b*HHx))*LL + qq)*LL + kk;
    #pragma unroll
    for(int h=0; h<HHx; h++){
        const float* w = &swz[h*CZx];
        float acc = 0.f;
        #pragma unroll
        for(int i=0;i<16;i++){
            acc += zv[i].x*w[4*i+0] + zv[i].y*w[4*i+1] + zv[i].z*w[4*i+2] + zv[i].w*w[4*i+3];
        }
        g_bias[obase + (size_t)h*LL*LL] = acc;
    }
}

// ---------------- logits: g_bias <- scale*QK^T + g_bias, pair-masked ----------------
__global__ void __launch_bounds__(256) k_logits(){
    __shared__ float Qs[32][68];
    __shared__ float Ks[32][68];
    int bh = blockIdx.z;
    int b = bh >> 4;
    int m0 = blockIdx.y*64, n0 = blockIdx.x*64;
    const float* Q = g_q + (size_t)bh*LL*DDx;
    const float* K = g_k + (size_t)bh*LL*DDx;
    int t = threadIdx.x, ty = t>>4, tx = t&15;
    #pragma unroll
    for(int i=0;i<2;i++){
        int lin = t + 256*i;
        int row = lin>>3, c4 = (lin&7)*4;
        float4 qv = *(const float4*)(Q + (size_t)(m0+row)*DDx + c4);
        float4 kv = *(const float4*)(K + (size_t)(n0+row)*DDx + c4);
        Qs[c4+0][row]=qv.x; Qs[c4+1][row]=qv.y; Qs[c4+2][row]=qv.z; Qs[c4+3][row]=qv.w;
        Ks[c4+0][row]=kv.x; Ks[c4+1][row]=kv.y; Ks[c4+2][row]=kv.z; Ks[c4+3][row]=kv.w;
    }
    __syncthreads();
    float acc[4][4] = {};
    #pragma unroll
    for(int kk=0; kk<32; kk++){
        float4 a4 = *(const float4*)&Qs[kk][ty*4];
        float4 b4 = *(const float4*)&Ks[kk][tx*4];
        float aa[4] = {a4.x,a4.y,a4.z,a4.w};
        float bb[4] = {b4.x,b4.y,b4.z,b4.w};
        #pragma unroll
        for(int i=0;i<4;i++)
            #pragma unroll
            for(int j=0;j<4;j++)
                acc[i][j] += aa[i]*bb[j];
    }
    const float SC = 0.17677669529663687f;   // 1/sqrt(32)
    #pragma unroll
    for(int i=0;i<4;i++){
        int m = m0 + ty*4 + i;
        float mq = g_maskf[b*LL + m];
        #pragma unroll
        for(int j=0;j<4;j++){
            int n = n0 + tx*4 + j;
            size_t idx = ((size_t)bh*LL + m)*LL + n;
            float v = acc[i][j]*SC + g_bias[idx];
            float pm = mq * g_maskf[b*LL + n];
            g_bias[idx] = (pm > 0.5f) ? v : -10000.0f;
        }
    }
}

// ---------------- softmax per row (exact reference semantics) ----------------
__global__ void __launch_bounds__(256) k_softmax(){
    __shared__ float sm[16];
    int row = blockIdx.x;                 // over B*H*L = 32768
    int b = row >> 14;
    float* p = g_bias + (size_t)row*LL;
    int t = threadIdx.x;
    float4 x = *(const float4*)(p + t*4);
    float mx = fmaxf(fmaxf(x.x,x.y), fmaxf(x.z,x.w));
    mx = blockRedMax(mx, sm);
    float4 mf = *(const float4*)(g_maskf + b*LL + t*4);
    float4 e;
    e.x = expf(x.x - mx); e.y = expf(x.y - mx);
    e.z = expf(x.z - mx); e.w = expf(x.w - mx);
    float se = e.x + e.y + e.z + e.w;
    float4 em;
    em.x = e.x*mf.x; em.y = e.y*mf.y; em.z = e.z*mf.z; em.w = e.w*mf.w;
    float semf = em.x + em.y + em.z + em.w;
    se   = blockRedSum(se, sm);
    semf = blockRedSum(semf, sm);
    // final = e*mf / max(sum(e*mf), 1e-6*sum(e))
    float inv = 1.f / fmaxf(semf, 1e-6f*se);
    float4 o;
    o.x = em.x*inv; o.y = em.y*inv; o.z = em.z*inv; o.w = em.w*inv;
    *(float4*)(p + t*4) = o;
}

// ---------------- PV: g_o1[b,q, h*32+d] = (P @ V) * gate ----------------
__global__ void __launch_bounds__(256) k_pv(){
    __shared__ float Ps[64][68];
    __shared__ float Vs[64][36];
    int bh = blockIdx.y;
    int b = bh >> 4, h = bh & 15;
    int m0 = blockIdx.x*64;
    const float* P = g_bias + (size_t)bh*LL*LL;
    const float* V = g_v + (size_t)bh*LL*DDx;
    int t = threadIdx.x, ty = t>>4, tx = t&15;
    float acc[4][2] = {};
    for(int kt=0; kt<LL; kt+=64){
        #pragma unroll
        for(int i=0;i<4;i++){
            int lin = t + 256*i;
            int row = lin>>4, c4 = (lin&15)*4;
            float4 pv = *(const float4*)(P + (size_t)(m0+row)*LL + kt + c4);
            Ps[c4+0][row]=pv.x; Ps[c4+1][row]=pv.y; Ps[c4+2][row]=pv.z; Ps[c4+3][row]=pv.w;
        }
        #pragma unroll
        for(int i=0;i<2;i++){
            int lin = t + 256*i;
            int krow = lin>>3, c4 = (lin&7)*4;
            float4 vv = *(const float4*)(V + (size_t)(kt+krow)*DDx + c4);
            *(float4*)&Vs[krow][c4] = vv;
        }
        __syncthreads();
        #pragma unroll
        for(int kk=0; kk<64; kk++){
            float4 a4 = *(const float4*)&Ps[kk][ty*4];
            float2 b2 = *(const float2*)&Vs[kk][tx*2];
            float aa[4] = {a4.x,a4.y,a4.z,a4.w};
            #pragma unroll
            for(int i=0;i<4;i++){
                acc[i][0] += aa[i]*b2.x;
                acc[i][1] += aa[i]*b2.y;
            }
        }
        __syncthreads();
    }
    #pragma unroll
    for(int i=0;i<4;i++){
        #pragma unroll
        for(int j=0;j<2;j++){
            int m = m0 + ty*4 + i;
            int n = tx*2 + j;
            size_t gidx = ((size_t)(b*LL + m))*CAx + h*DDx + n;
            g_o1[gidx] = acc[i][j] * g_gate[gidx];
        }
    }
}

// ---------------- launch ----------------
extern "C" void kernel_launch(void* const* d_in, const int* in_sizes, int n_in,
                              void* d_out, int out_size){
    const float* a          = (const float*)d_in[0];
    const float* s          = (const float*)d_in[1];
    const float* z          = (const float*)d_in[2];
    const float* ln_s_scale = (const float*)d_in[3];
    const float* ada_w_s    = (const float*)d_in[4];
    const float* ada_b_s    = (const float*)d_in[5];
    const float* ada_w_nb   = (const float*)d_in[6];
    const float* wq = (const float*)d_in[7];   const float* bq = (const float*)d_in[8];
    const float* wk = (const float*)d_in[9];   const float* bk = (const float*)d_in[10];
    const float* wv = (const float*)d_in[11];  const float* bv = (const float*)d_in[12];
    const float* wg = (const float*)d_in[13];  const float* bg = (const float*)d_in[14];
    const float* wo = (const float*)d_in[15];  const float* bo = (const float*)d_in[16];
    const float* ln_z_scale = (const float*)d_in[17];
    const float* wz         = (const float*)d_in[18];
    const float* w_last     = (const float*)d_in[19];
    const float* b_last     = (const float*)d_in[20];
    const unsigned int* mask = (const unsigned int*)d_in[21];
    float* out = (float*)d_out;

    float *p_sln, *p_anorm, *p_t1, *p_t2, *p_q, *p_k, *p_v, *p_gate, *p_o1, *p_o2, *p_maskf;
    cudaGetSymbolAddress((void**)&p_sln,   g_sln);
    cudaGetSymbolAddress((void**)&p_anorm, g_anorm);
    cudaGetSymbolAddress((void**)&p_t1,    g_t1);
    cudaGetSymbolAddress((void**)&p_t2,    g_t2);
    cudaGetSymbolAddress((void**)&p_q,     g_q);
    cudaGetSymbolAddress((void**)&p_k,     g_k);
    cudaGetSymbolAddress((void**)&p_v,     g_v);
    cudaGetSymbolAddress((void**)&p_gate,  g_gate);
    cudaGetSymbolAddress((void**)&p_o1,    g_o1);
    cudaGetSymbolAddress((void**)&p_o2,    g_o2);
    cudaGetSymbolAddress((void**)&p_maskf, g_maskf);

    k_maskf<<<(MMx+255)/256, 256>>>(mask);
    k_ln<<<MMx, 256>>>(a, s, ln_s_scale);

    dim3 gA(CAx/64, MMx/64);   // (8, 32)
    gemm64<0><<<gA, 256>>>(p_sln, ada_w_s,  ada_b_s, p_t1, CAx, CSx, nullptr, nullptr);
    gemm64<0><<<gA, 256>>>(p_sln, ada_w_nb, nullptr, p_t2, CAx, CSx, nullptr, nullptr);
    k_anorm<<<(MMx*CAx)/256, 256>>>();

    gemm64<1><<<gA, 256>>>(p_anorm, wq, bq, p_q,    CAx, CAx, nullptr, nullptr);
    gemm64<1><<<gA, 256>>>(p_anorm, wk, bk, p_k,    CAx, CAx, nullptr, nullptr);
    gemm64<1><<<gA, 256>>>(p_anorm, wv, bv, p_v,    CAx, CAx, nullptr, nullptr);
    gemm64<2><<<gA, 256>>>(p_anorm, wg, bg, p_gate, CAx, CAx, nullptr, nullptr);

    k_bias<<<(BB*LL*LL)/256, 256>>>(z, ln_z_scale, wz);

    dim3 gL(LL/64, LL/64, BB*HHx);   // (16,16,32)
    k_logits<<<gL, 256>>>();

    k_softmax<<<BB*HHx*LL, 256>>>();

    dim3 gP(LL/64, BB*HHx);          // (16, 32)
    k_pv<<<gP, 256>>>();

    gemm64<0><<<gA, 256>>>(p_o1, wo, bo, p_o2, CAx, CAx, nullptr, nullptr);
    gemm64<3><<<gA, 256>>>(s, w_last, b_last, out, CAx, CSx, p_o2, p_maskf);
}

// round 4
// speedup vs baseline: 1.5188x; 1.5188x over previous
#include <cuda_runtime.h>
#include <math.h>
#include <stdint.h>

// Problem constants
#define BB 2
#define LL 1024
#define CAx 512
#define CSx 384
#define CZx 64
#define HHx 16
#define DDx 32
#define MMx (BB*LL)   // 2048

// ---------------- scratch (static device memory; no allocations) ----------------
__device__ float g_aln[MMx*CAx];
__device__ float g_sln[MMx*CSx];
__device__ float g_anorm[MMx*CAx];
__device__ float g_t1[MMx*CAx];
__device__ float g_t2[MMx*CAx];
__device__ float g_q[BB*HHx*LL*DDx];
__device__ float g_k[BB*HHx*LL*DDx];
__device__ float g_v[BB*HHx*LL*DDx];
__device__ float g_gate[MMx*CAx];
__device__ float g_o1[MMx*CAx];
__device__ float g_o2[MMx*CAx];
__device__ float g_maskf[MMx];
__device__ float g_bias[(size_t)BB*HHx*LL*LL];  // 128 MB; bias -> logits -> probs

// ---------------- tf32 mma helpers ----------------
__device__ __forceinline__ uint32_t f2t(float x){
    uint32_t u; asm("cvt.rna.tf32.f32 %0, %1;" : "=r"(u) : "f"(x)); return u;
}
__device__ __forceinline__ uint4 f2t4(float4 v){
    uint4 r; r.x=f2t(v.x); r.y=f2t(v.y); r.z=f2t(v.z); r.w=f2t(v.w); return r;
}
// D += A(16x8,row) * B(8x8,col);  c[4] in-place
__device__ __forceinline__ void mma8(float* c, const uint32_t* a, const uint32_t* b){
    asm volatile(
        "mma.sync.aligned.m16n8k8.row.col.f32.tf32.tf32.f32 "
        "{%0,%1,%2,%3},{%4,%5,%6,%7},{%8,%9},{%0,%1,%2,%3};\n"
        : "+f"(c[0]), "+f"(c[1]), "+f"(c[2]), "+f"(c[3])
        : "r"(a[0]), "r"(a[1]), "r"(a[2]), "r"(a[3]), "r"(b[0]), "r"(b[1]));
}

// ---------------- reductions ----------------
__device__ __forceinline__ float warpRedSum(float v){
    #pragma unroll
    for(int o=16;o>0;o>>=1) v += __shfl_xor_sync(0xffffffffu, v, o);
    return v;
}
__device__ __forceinline__ float warpRedMax(float v){
    #pragma unroll
    for(int o=16;o>0;o>>=1) v = fmaxf(v, __shfl_xor_sync(0xffffffffu, v, o));
    return v;
}
__device__ float blockRedSum(float v, float* sm){
    int lane = threadIdx.x & 31, w = threadIdx.x >> 5;
    v = warpRedSum(v);
    if(lane==0) sm[w] = v;
    __syncthreads();
    if(w==0){
        float x = (lane<8)? sm[lane] : 0.f;
        x = warpRedSum(x);
        if(lane==0) sm[8] = x;
    }
    __syncthreads();
    float r = sm[8];
    __syncthreads();
    return r;
}
__device__ float blockRedMax(float v, float* sm){
    int lane = threadIdx.x & 31, w = threadIdx.x >> 5;
    v = warpRedMax(v);
    if(lane==0) sm[w] = v;
    __syncthreads();
    if(w==0){
        float x = (lane<8)? sm[lane] : -3.4e38f;
        x = warpRedMax(x);
        if(lane==0) sm[8] = x;
    }
    __syncthreads();
    float r = sm[8];
    __syncthreads();
    return r;
}

__device__ __forceinline__ float sigm(float v){ return 1.f/(1.f+expf(-v)); }

// ---------------- mask -> float (mask arrives as 4-byte dtype) ----------------
__global__ void k_maskf(const unsigned int* __restrict__ mk){
    int i = blockIdx.x*256 + threadIdx.x;
    if(i < MMx) g_maskf[i] = (mk[i] != 0u) ? 1.f : 0.f;
}

// ---------------- LayerNorm of a (512) and s (384, scaled) ----------------
__global__ void __launch_bounds__(256) k_ln(const float* __restrict__ a,
                                            const float* __restrict__ s,
                                            const float* __restrict__ lns){
    __shared__ float sm[16];
    int m = blockIdx.x, t = threadIdx.x;
    const float* ar = a + (size_t)m*CAx;
    float x0 = ar[t], x1 = ar[t+256];
    float sum  = blockRedSum(x0 + x1, sm);
    float sum2 = blockRedSum(x0*x0 + x1*x1, sm);
    float mean = sum * (1.f/CAx);
    float var  = sum2 * (1.f/CAx) - mean*mean;
    float r = rsqrtf(var + 1e-5f);
    g_aln[(size_t)m*CAx + t]       = (x0-mean)*r;
    g_aln[(size_t)m*CAx + t + 256] = (x1-mean)*r;
    const float* sr = s + (size_t)m*CSx;
    float y0 = sr[t];
    float y1 = (t < 128) ? sr[t+256] : 0.f;
    float ss  = blockRedSum(y0 + y1, sm);
    float ss2 = blockRedSum(y0*y0 + y1*y1, sm);
    float mn = ss * (1.f/CSx);
    float vr = ss2 * (1.f/CSx) - mn*mn;
    float rr = rsqrtf(vr + 1e-5f);
    g_sln[(size_t)m*CSx + t] = (y0-mn)*rr*lns[t];
    if(t < 128) g_sln[(size_t)m*CSx + t + 256] = (y1-mn)*rr*lns[t+256];
}

// ---------------- tf32 tensor-core GEMM: out = A[M,K] @ W[N,K]^T (+bias) ----------------
// Tiles: BM=64, BN=64, BK=32. 256 threads = 8 warps (4 m x 2 n), warp tile 16x32.
// EPI: 0 plain; 1 head layout [B,H,L,D]; 2 sigmoid; 3 sigmoid(v)*aux1*aux2[m]
template<int EPI>
__global__ void __launch_bounds__(256) gemm_tc(const float* __restrict__ A,
                                               const float* __restrict__ W,
                                               const float* __restrict__ bias,
                                               float* __restrict__ out,
                                               int N, int K,
                                               const float* __restrict__ aux1,
                                               const float* __restrict__ aux2){
    __shared__ uint32_t As[2][64][36];
    __shared__ uint32_t Ws[2][64][36];
    int t = threadIdx.x;
    int lane = t & 31, wid = t >> 5;
    int gid = lane >> 2, tig = lane & 3;
    int warpM = wid & 3, warpN = wid >> 2;
    int m0 = blockIdx.y*64, n0 = blockIdx.x*64;
    // gmem->smem mapping: 2 float4 chunks per thread per matrix
    int r0 = t >> 3, cc = (t & 7) * 4;        // rows 0..31
    int r1 = r0 + 32;                          // rows 32..63
    const float* Ap0 = A + (size_t)(m0+r0)*K + cc;
    const float* Ap1 = A + (size_t)(m0+r1)*K + cc;
    const float* Wp0 = W + (size_t)(n0+r0)*K + cc;
    const float* Wp1 = W + (size_t)(n0+r1)*K + cc;

    // preload tile 0
    {
        float4 a0v = *(const float4*)Ap0;
        float4 a1v = *(const float4*)Ap1;
        float4 w0v = *(const float4*)Wp0;
        float4 w1v = *(const float4*)Wp1;
        *(uint4*)&As[0][r0][cc] = f2t4(a0v);
        *(uint4*)&As[0][r1][cc] = f2t4(a1v);
        *(uint4*)&Ws[0][r0][cc] = f2t4(w0v);
        *(uint4*)&Ws[0][r1][cc] = f2t4(w1v);
    }
    __syncthreads();

    float c[4][4] = {};
    int buf = 0;
    for(int kt=0; kt<K; kt+=32){
        bool nxt = (kt+32) < K;
        float4 na0, na1, nw0, nw1;
        if(nxt){
            na0 = *(const float4*)(Ap0 + kt + 32);
            na1 = *(const float4*)(Ap1 + kt + 32);
            nw0 = *(const float4*)(Wp0 + kt + 32);
            nw1 = *(const float4*)(Wp1 + kt + 32);
        }
        #pragma unroll
        for(int ks=0; ks<4; ks++){
            uint32_t af[4];
            int arow = warpM*16 + gid;
            af[0] = As[buf][arow  ][ks*8+tig  ];
            af[1] = As[buf][arow+8][ks*8+tig  ];
            af[2] = As[buf][arow  ][ks*8+tig+4];
            af[3] = As[buf][arow+8][ks*8+tig+4];
            #pragma unroll
            for(int nt=0; nt<4; nt++){
                uint32_t bf[2];
                int brow = warpN*32 + nt*8 + gid;
                bf[0] = Ws[buf][brow][ks*8+tig  ];
                bf[1] = Ws[buf][brow][ks*8+tig+4];
                mma8(c[nt], af, bf);
            }
        }
        if(nxt){
            int nb = buf ^ 1;
            *(uint4*)&As[nb][r0][cc] = f2t4(na0);
            *(uint4*)&As[nb][r1][cc] = f2t4(na1);
            *(uint4*)&Ws[nb][r0][cc] = f2t4(nw0);
            *(uint4*)&Ws[nb][r1][cc] = f2t4(nw1);
            __syncthreads();
            buf = nb;
        }
    }

    // epilogue: c[nt][0..1] -> row m, cols 2tig,2tig+1 ; c[nt][2..3] -> row m+8
    #pragma unroll
    for(int nt=0; nt<4; nt++){
        int n = n0 + warpN*32 + nt*8 + 2*tig;
        float bn0 = bias ? bias[n]   : 0.f;
        float bn1 = bias ? bias[n+1] : 0.f;
        #pragma unroll
        for(int rr=0; rr<2; rr++){
            int m = m0 + warpM*16 + gid + rr*8;
            float v0 = c[nt][rr*2+0] + bn0;
            float v1 = c[nt][rr*2+1] + bn1;
            if(EPI==0){
                float2 o = make_float2(v0, v1);
                *(float2*)&out[(size_t)m*N + n] = o;
            } else if(EPI==1){
                int b = m>>10, l = m&1023, h = n>>5, d = n&31;
                float2 o = make_float2(v0, v1);
                *(float2*)&out[(((size_t)(b*HHx+h))*LL + l)*DDx + d] = o;
            } else if(EPI==2){
                float2 o = make_float2(sigm(v0), sigm(v1));
                *(float2*)&out[(size_t)m*N + n] = o;
            } else {
                float2 ax = *(const float2*)&aux1[(size_t)m*N + n];
                float a2 = aux2[m];
                float2 o = make_float2(sigm(v0)*ax.x*a2, sigm(v1)*ax.y*a2);
                *(float2*)&out[(size_t)m*N + n] = o;
            }
        }
    }
}

// ---------------- a_norm = sigmoid(t1)*a_ln + t2 ----------------
__global__ void k_anorm(){
    int i = blockIdx.x*256 + threadIdx.x;
    g_anorm[i] = sigm(g_t1[i]) * g_aln[i] + g_t2[i];
}

// ---------------- pair bias via tf32 MMA ----------------
// Block: 256 threads, handles 128 consecutive z rows (same b,q; k range of 128).
// LN each row (thread pairs), project to 16 heads with MMA, coalesced scatter.
__global__ void __launch_bounds__(256) k_bias_tc(const float* __restrict__ z,
                                                 const float* __restrict__ lnz,
                                                 const float* __restrict__ wz){
    __shared__ uint32_t Zs[128][68];
    __shared__ uint32_t wzs[16][68];
    __shared__ float Cs[16][132];
    __shared__ float sscale[CZx];
    int t = threadIdx.x;
    int lane = t & 31, wid = t >> 5;
    int gid = lane >> 2, tig = lane & 3;

    // stage wz (16x64) as tf32 and lnz scales
    {
        int row = t >> 4, c4 = (t & 15) * 4;   // 256 threads -> 16x64 exactly
        float4 w4 = *(const float4*)&wz[row*CZx + c4];
        *(uint4*)&wzs[row][c4] = f2t4(w4);
    }
    if(t < CZx) sscale[t] = lnz[t];

    // LN: thread pair (2r,2r+1) handles row r; each loads 32 floats
    size_t r0 = (size_t)blockIdx.x * 128;
    int row = t >> 1, half = t & 1;
    const float4* zp = (const float4*)(z + (r0 + row)*CZx + half*32);
    float4 zv[8];
    float sum = 0.f, sum2 = 0.f;
    #pragma unroll
    for(int i=0;i<8;i++){
        zv[i] = zp[i];
        sum  += zv[i].x + zv[i].y + zv[i].z + zv[i].w;
        sum2 += zv[i].x*zv[i].x + zv[i].y*zv[i].y + zv[i].z*zv[i].z + zv[i].w*zv[i].w;
    }
    sum  += __shfl_xor_sync(0xffffffffu, sum, 1);
    sum2 += __shfl_xor_sync(0xffffffffu, sum2, 1);
    float mean = sum * (1.f/CZx);
    float var  = sum2 * (1.f/CZx) - mean*mean;
    float rs = rsqrtf(var + 1e-5f);
    __syncthreads();   // sscale + wzs ready
    #pragma unroll
    for(int i=0;i<8;i++){
        int cbase = half*32 + i*4;
        uint4 u;
        u.x = f2t((zv[i].x-mean)*rs*sscale[cbase+0]);
        u.y = f2t((zv[i].y-mean)*rs*sscale[cbase+1]);
        u.z = f2t((zv[i].z-mean)*rs*sscale[cbase+2]);
        u.w = f2t((zv[i].w-mean)*rs*sscale[cbase+3]);
        *(uint4*)&Zs[row][cbase] = u;
    }
    __syncthreads();

    // MMA: [128 x 64] @ wz^T[64 x 16] ; warp wid owns rows wid*16..+15
    float c[2][4] = {};
    #pragma unroll
    for(int ks=0; ks<8; ks++){
        uint32_t af[4];
        int arow = wid*16 + gid;
        af[0] = Zs[arow  ][ks*8+tig  ];
        af[1] = Zs[arow+8][ks*8+tig  ];
        af[2] = Zs[arow  ][ks*8+tig+4];
        af[3] = Zs[arow+8][ks*8+tig+4];
        #pragma unroll
        for(int nt=0; nt<2; nt++){
            uint32_t bf[2];
            bf[0] = wzs[nt*8+gid][ks*8+tig  ];
            bf[1] = wzs[nt*8+gid][ks*8+tig+4];
            mma8(c[nt], af, bf);
        }
    }
    // transpose through smem for coalesced global writes
    #pragma unroll
    for(int nt=0; nt<2; nt++){
        int h0 = nt*8 + 2*tig;
        Cs[h0  ][wid*16+gid  ] = c[nt][0];
        Cs[h0+1][wid*16+gid  ] = c[nt][1];
        Cs[h0  ][wid*16+gid+8] = c[nt][2];
        Cs[h0+1][wid*16+gid+8] = c[nt][3];
    }
    __syncthreads();

    int b  = (int)(r0 >> 20);
    int qq = (int)((r0 >> 10) & 1023);
    int k0 = (int)(r0 & 1023);
    int h = t >> 4, chunk = t & 15;       // 8 floats each
    float* dst = &g_bias[(((size_t)(b*HHx+h))*LL + qq)*LL + k0 + chunk*8];
    float4 o0, o1;
    o0.x = Cs[h][chunk*8+0]; o0.y = Cs[h][chunk*8+1];
    o0.z = Cs[h][chunk*8+2]; o0.w = Cs[h][chunk*8+3];
    o1.x = Cs[h][chunk*8+4]; o1.y = Cs[h][chunk*8+5];
    o1.z = Cs[h][chunk*8+6]; o1.w = Cs[h][chunk*8+7];
    *(float4*)dst = o0;
    *(float4*)(dst+4) = o1;
}

// ---------------- logits via tf32 MMA: g_bias <- scale*QK^T + g_bias, masked ----------------
// 128 threads = 4 warps; tile 64q x 64k per (b,h)
__global__ void __launch_bounds__(128) k_logits_tc(){
    __shared__ uint32_t Qs[64][36];
    __shared__ uint32_t Ks[64][36];
    __shared__ float smq[64], smk[64];
    int bh = blockIdx.z;
    int b = bh >> 4;
    int m0 = blockIdx.y*64, n0 = blockIdx.x*64;
    const float* Q = g_q + (size_t)bh*LL*DDx;
    const float* Kk = g_k + (size_t)bh*LL*DDx;
    int t = threadIdx.x;
    int lane = t & 31, wid = t >> 5;
    int gid = lane >> 2, tig = lane & 3;

    #pragma unroll
    for(int i=0;i<4;i++){
        int cidx = t + i*128;
        int row = cidx >> 3, c4 = (cidx & 7) * 4;
        float4 qv = *(const float4*)(Q + (size_t)(m0+row)*DDx + c4);
        float4 kv = *(const float4*)(Kk + (size_t)(n0+row)*DDx + c4);
        *(uint4*)&Qs[row][c4] = f2t4(qv);
        *(uint4*)&Ks[row][c4] = f2t4(kv);
    }
    if(t < 64){
        smq[t] = g_maskf[b*LL + m0 + t];
        smk[t] = g_maskf[b*LL + n0 + t];
    }
    __syncthreads();

    float c[8][4] = {};
    #pragma unroll
    for(int ks=0; ks<4; ks++){
        uint32_t af[4];
        int arow = wid*16 + gid;
        af[0] = Qs[arow  ][ks*8+tig  ];
        af[1] = Qs[arow+8][ks*8+tig  ];
        af[2] = Qs[arow  ][ks*8+tig+4];
        af[3] = Qs[arow+8][ks*8+tig+4];
        #pragma unroll
        for(int nt=0; nt<8; nt++){
            uint32_t bf[2];
            bf[0] = Ks[nt*8+gid][ks*8+tig  ];
            bf[1] = Ks[nt*8+gid][ks*8+tig+4];
            mma8(c[nt], af, bf);
        }
    }

    const float SC = 0.17677669529663687f;   // 1/sqrt(32)
    #pragma unroll
    for(int nt=0; nt<8; nt++){
        int nn = nt*8 + 2*tig;
        int n = n0 + nn;
        float mk0 = smk[nn], mk1 = smk[nn+1];
        #pragma unroll
        for(int rr=0; rr<2; rr++){
            int ml = wid*16 + gid + rr*8;
            int m = m0 + ml;
            float mq = smq[ml];
            size_t idx = ((size_t)bh*LL + m)*LL + n;
            float2 bv = *(const float2*)&g_bias[idx];
            float v0 = c[nt][rr*2+0]*SC + bv.x;
            float v1 = c[nt][rr*2+1]*SC + bv.y;
            float2 o;
            o.x = (mq*mk0 > 0.5f) ? v0 : -10000.0f;
            o.y = (mq*mk1 > 0.5f) ? v1 : -10000.0f;
            *(float2*)&g_bias[idx] = o;
        }
    }
}

// ---------------- softmax per row (exact reference semantics) ----------------
__global__ void __launch_bounds__(256) k_softmax(){
    __shared__ float sm[16];
    int row = blockIdx.x;                 // over B*H*L
    int b = row >> 14;
    float* p = g_bias + (size_t)row*LL;
    int t = threadIdx.x;
    float4 x = *(const float4*)(p + t*4);
    float mx = fmaxf(fmaxf(x.x,x.y), fmaxf(x.z,x.w));
    mx = blockRedMax(mx, sm);
    float4 mf = *(const float4*)(g_maskf + b*LL + t*4);
    float4 e;
    e.x = expf(x.x - mx); e.y = expf(x.y - mx);
    e.z = expf(x.z - mx); e.w = expf(x.w - mx);
    float se = e.x + e.y + e.z + e.w;
    float4 em;
    em.x = e.x*mf.x; em.y = e.y*mf.y; em.z = e.z*mf.z; em.w = e.w*mf.w;
    float semf = em.x + em.y + em.z + em.w;
    se   = blockRedSum(se, sm);
    semf = blockRedSum(semf, sm);
    float inv = 1.f / fmaxf(semf, 1e-6f*se);
    float4 o;
    o.x = em.x*inv; o.y = em.y*inv; o.z = em.z*inv; o.w = em.w*inv;
    *(float4*)(p + t*4) = o;
}

// ---------------- PV via tf32 MMA: g_o1 = (P @ V) * gate ----------------
// 128 threads = 4 warps; out tile 64q x 32d per (b,h)
__global__ void __launch_bounds__(128) k_pv_tc(){
    __shared__ uint32_t Ps[64][68];
    __shared__ uint32_t Vt[32][68];   // transposed: [d][k]
    int bh = blockIdx.y;
    int b = bh >> 4, h = bh & 15;
    int m0 = blockIdx.x*64;
    const float* P = g_bias + (size_t)bh*LL*LL;
    const float* V = g_v + (size_t)bh*LL*DDx;
    int t = threadIdx.x;
    int lane = t & 31, wid = t >> 5;
    int gid = lane >> 2, tig = lane & 3;

    float c[4][4] = {};
    for(int kt=0; kt<LL; kt+=64){
        __syncthreads();
        #pragma unroll
        for(int i=0;i<8;i++){
            int cidx = t + i*128;
            int row = cidx >> 4, c4 = (cidx & 15) * 4;
            float4 pv = *(const float4*)(P + (size_t)(m0+row)*LL + kt + c4);
            *(uint4*)&Ps[row][c4] = f2t4(pv);
        }
        #pragma unroll
        for(int i=0;i<4;i++){
            int cidx = t + i*128;
            int krow = cidx >> 3, d4 = (cidx & 7) * 4;
            float4 vv = *(const float4*)(V + (size_t)(kt+krow)*DDx + d4);
            Vt[d4+0][krow] = f2t(vv.x);
            Vt[d4+1][krow] = f2t(vv.y);
            Vt[d4+2][krow] = f2t(vv.z);
            Vt[d4+3][krow] = f2t(vv.w);
        }
        __syncthreads();
        #pragma unroll
        for(int ks=0; ks<8; ks++){
            uint32_t af[4];
            int arow = wid*16 + gid;
            af[0] = Ps[arow  ][ks*8+tig  ];
            af[1] = Ps[arow+8][ks*8+tig  ];
            af[2] = Ps[arow  ][ks*8+tig+4];
            af[3] = Ps[arow+8][ks*8+tig+4];
            #pragma unroll
            for(int nt=0; nt<4; nt++){
                uint32_t bf[2];
                bf[0] = Vt[nt*8+gid][ks*8+tig  ];
                bf[1] = Vt[nt*8+gid][ks*8+tig+4];
                mma8(c[nt], af, bf);
            }
        }
    }
    #pragma unroll
    for(int nt=0; nt<4; nt++){
        int d = nt*8 + 2*tig;
        #pragma unroll
        for(int rr=0; rr<2; rr++){
            int m = m0 + wid*16 + gid + rr*8;
            size_t gidx = ((size_t)(b*LL + m))*CAx + h*DDx + d;
            float2 g = *(const float2*)&g_gate[gidx];
            float2 o = make_float2(c[nt][rr*2+0]*g.x, c[nt][rr*2+1]*g.y);
            *(float2*)&g_o1[gidx] = o;
        }
    }
}

// ---------------- launch ----------------
extern "C" void kernel_launch(void* const* d_in, const int* in_sizes, int n_in,
                              void* d_out, int out_size){
    const float* a          = (const float*)d_in[0];
    const float* s          = (const float*)d_in[1];
    const float* z          = (const float*)d_in[2];
    const float* ln_s_scale = (const float*)d_in[3];
    const float* ada_w_s    = (const float*)d_in[4];
    const float* ada_b_s    = (const float*)d_in[5];
    const float* ada_w_nb   = (const float*)d_in[6];
    const float* wq = (const float*)d_in[7];   const float* bq = (const float*)d_in[8];
    const float* wk = (const float*)d_in[9];   const float* bk = (const float*)d_in[10];
    const float* wv = (const float*)d_in[11];  const float* bv = (const float*)d_in[12];
    const float* wg = (const float*)d_in[13];  const float* bg = (const float*)d_in[14];
    const float* wo = (const float*)d_in[15];  const float* bo = (const float*)d_in[16];
    const float* ln_z_scale = (const float*)d_in[17];
    const float* wz         = (const float*)d_in[18];
    const float* w_last     = (const float*)d_in[19];
    const float* b_last     = (const float*)d_in[20];
    const unsigned int* mask = (const unsigned int*)d_in[21];
    float* out = (float*)d_out;

    float *p_sln, *p_anorm, *p_t1, *p_t2, *p_q, *p_k, *p_v, *p_gate, *p_o1, *p_o2, *p_maskf;
    cudaGetSymbolAddress((void**)&p_sln,   g_sln);
    cudaGetSymbolAddress((void**)&p_anorm, g_anorm);
    cudaGetSymbolAddress((void**)&p_t1,    g_t1);
    cudaGetSymbolAddress((void**)&p_t2,    g_t2);
    cudaGetSymbolAddress((void**)&p_q,     g_q);
    cudaGetSymbolAddress((void**)&p_k,     g_k);
    cudaGetSymbolAddress((void**)&p_v,     g_v);
    cudaGetSymbolAddress((void**)&p_gate,  g_gate);
    cudaGetSymbolAddress((void**)&p_o1,    g_o1);
    cudaGetSymbolAddress((void**)&p_o2,    g_o2);
    cudaGetSymbolAddress((void**)&p_maskf, g_maskf);

    k_maskf<<<(MMx+255)/256, 256>>>(mask);
    k_ln<<<MMx, 256>>>(a, s, ln_s_scale);

    dim3 gA(CAx/64, MMx/64);   // (8, 32)
    gemm_tc<0><<<gA, 256>>>(p_sln, ada_w_s,  ada_b_s, p_t1, CAx, CSx, nullptr, nullptr);
    gemm_tc<0><<<gA, 256>>>(p_sln, ada_w_nb, nullptr, p_t2, CAx, CSx, nullptr, nullptr);
    k_anorm<<<(MMx*CAx)/256, 256>>>();

    gemm_tc<1><<<gA, 256>>>(p_anorm, wq, bq, p_q,    CAx, CAx, nullptr, nullptr);
    gemm_tc<1><<<gA, 256>>>(p_anorm, wk, bk, p_k,    CAx, CAx, nullptr, nullptr);
    gemm_tc<1><<<gA, 256>>>(p_anorm, wv, bv, p_v,    CAx, CAx, nullptr, nullptr);
    gemm_tc<2><<<gA, 256>>>(p_anorm, wg, bg, p_gate, CAx, CAx, nullptr, nullptr);

    k_bias_tc<<<(BB*LL*LL)/128, 256>>>(z, ln_z_scale, wz);

    dim3 gL(LL/64, LL/64, BB*HHx);   // (16,16,32)
    k_logits_tc<<<gL, 128>>>();

    k_softmax<<<BB*HHx*LL, 256>>>();

    dim3 gP(LL/64, BB*HHx);          // (16, 32)
    k_pv_tc<<<gP, 128>>>();

    gemm_tc<0><<<gA, 256>>>(p_o1, wo, bo, p_o2, CAx, CAx, nullptr, nullptr);
    gemm_tc<3><<<gA, 256>>>(s, w_last, b_last, out, CAx, CSx, p_o2, p_maskf);
}